// round 16
// baseline (speedup 1.0000x reference)
#include <cuda_runtime.h>
#include <cuda_fp16.h>
#include <math.h>

#define BB   16
#define SSZ  1024
#define DDIM 512
#define PDIM 256            // packed fp16 pairs per row
#define BSN  (BB*SSZ)       // 16384 rows
#define NEGF (-1e30f)

// ---------------- scratch (device globals: allocation-free) ----------------
__device__ unsigned g_conv[BSN*PDIM];        // conv residual, packed fp16
__device__ float    g_res [BSN*DDIM];
__device__ unsigned g_n1[BSN*PDIM];
__device__ unsigned g_d [BSN*PDIM];
__device__ unsigned g_q [BSN*PDIM];
__device__ unsigned g_k [BSN*PDIM];
__device__ unsigned g_v [BSN*PDIM];
__device__ unsigned g_a [BSN*PDIM];
__device__ unsigned g_wm[DDIM*PDIM];
__device__ unsigned g_wq[DDIM*PDIM];
__device__ unsigned g_wk[DDIM*PDIM];
__device__ unsigned g_wv[DDIM*PDIM];
__device__ unsigned g_wo[DDIM*PDIM];

// ---------------- helpers ----------------------------------------------------
__device__ __forceinline__ unsigned h2pk(float x0, float x1) {
    __half2 h = __floats2half2_rn(x0, x1);
    return *(unsigned*)&h;
}
__device__ __forceinline__ float2 h2up(unsigned u) {
    __half2 h = *(__half2*)&u;
    return __half22float2(h);
}
__device__ __forceinline__ void mma16(float* c, const unsigned* a, const unsigned* b) {
    asm volatile(
        "mma.sync.aligned.m16n8k16.row.col.f32.f16.f16.f32 "
        "{%0,%1,%2,%3}, {%4,%5,%6,%7}, {%8,%9}, {%0,%1,%2,%3};\n"
        : "+f"(c[0]), "+f"(c[1]), "+f"(c[2]), "+f"(c[3])
        : "r"(a[0]), "r"(a[1]), "r"(a[2]), "r"(a[3]), "r"(b[0]), "r"(b[1]));
}
__device__ __forceinline__ void ldsm_x4(unsigned& r0, unsigned& r1, unsigned& r2,
                                        unsigned& r3, unsigned addr) {
    asm volatile("ldmatrix.sync.aligned.m8n8.x4.shared.b16 {%0,%1,%2,%3}, [%4];"
        : "=r"(r0), "=r"(r1), "=r"(r2), "=r"(r3) : "r"(addr));
}
__device__ __forceinline__ void ldsm_x4t(unsigned& r0, unsigned& r1, unsigned& r2,
                                         unsigned& r3, unsigned addr) {
    asm volatile("ldmatrix.sync.aligned.m8n8.x4.trans.shared.b16 {%0,%1,%2,%3}, [%4];"
        : "=r"(r0), "=r"(r1), "=r"(r2), "=r"(r3) : "r"(addr));
}
__device__ __forceinline__ unsigned su32(const void* p) {
    return (unsigned)__cvta_generic_to_shared(p);
}
#define CP16(d, s) asm volatile("cp.async.cg.shared.global [%0], [%1], 16;\n" :: "r"(d), "l"(s))
#define CP_COMMIT()  asm volatile("cp.async.commit_group;\n")
#define CP_WAIT1()   asm volatile("cp.async.wait_group 1;\n")

// ---------------- kernel: fp32 -> packed fp16 for 5 weights ------------------
struct CvtTab { const float4* in[5]; uint2* o[5]; };
__global__ __launch_bounds__(256) void k_cvt5(CvtTab tab, int n4)
{
    const int w = blockIdx.y;
    int i = blockIdx.x * 256 + threadIdx.x;
    if (i >= n4) return;
    float4 v = tab.in[w][i];
    tab.o[w][i] = make_uint2(h2pk(v.x, v.y), h2pk(v.z, v.w));
}

// ---------------- kernel 1: conv + pe + gelu + LN1 -> packed fp16 ------------
// 2048 blocks x 256 threads; warp-per-row (8 rows per block).
__global__ __launch_bounds__(256) void k_embed2(
    const float* __restrict__ ts, const float* __restrict__ cw,
    const float* __restrict__ cb, const float* __restrict__ pe,
    const float* __restrict__ g1, const float* __restrict__ b1,
    unsigned* __restrict__ convo, unsigned* __restrict__ n1o)
{
    const int warp = threadIdx.x >> 5, lane = threadIdx.x & 31;
    const int bs = (blockIdx.x << 3) + warp;          // 8 rows per block
    const int b = bs >> 10, s = bs & 1023;
    const float* tp = ts + ((size_t)b << 12) + (s << 2);
    const float t0 = tp[0], t1 = tp[1], t2 = tp[2], t3 = tp[3];

    const int d0 = lane << 4;                         // 16 consecutive d
    float cv[16], act[16];
    float ls1 = 0.f, ls2 = 0.f;
#pragma unroll
    for (int j4 = 0; j4 < 4; j4++) {
        const float4 cb4 = *(const float4*)(cb + d0 + (j4 << 2));
        const float4 pe4 = *(const float4*)(pe + ((size_t)s << 9) + d0 + (j4 << 2));
#pragma unroll
        for (int j = 0; j < 4; j++) {
            const int jj = (j4 << 2) + j;
            const float4 w = *(const float4*)(cw + ((d0 + jj) << 2));
            float c = fmaf(t0, w.x, fmaf(t1, w.y, fmaf(t2, w.z, t3 * w.w)));
            c += ((const float*)&cb4)[j] + ((const float*)&pe4)[j];
            cv[jj] = c;
            const float a = 0.5f * c * (1.0f + erff(c * 0.70710678118654752f));
            act[jj] = a; ls1 += a; ls2 += a * a;
        }
    }
#pragma unroll
    for (int o = 16; o; o >>= 1) {
        ls1 += __shfl_xor_sync(0xffffffffu, ls1, o);
        ls2 += __shfl_xor_sync(0xffffffffu, ls2, o);
    }
    const float mean = ls1 * (1.0f / 512.0f);
    const float var  = (ls2 - 512.0f * mean * mean) * (1.0f / 511.0f);  // ddof=1
    const float rstd = rsqrtf(var + 1e-5f);
    const float gg = g1[s], be = b1[s];

    const size_t pr = ((size_t)bs << 8) + (lane << 3);
    uint4 cpk[2], npk[2];
#pragma unroll
    for (int h = 0; h < 2; h++) {
        unsigned cc[4], nn[4];
#pragma unroll
        for (int j = 0; j < 4; j++) {
            const int jj = (h << 3) + (j << 1);
            cc[j] = h2pk(cv[jj], cv[jj + 1]);
            const float v0 = gg * (act[jj]     - mean) * rstd + be;
            const float v1 = gg * (act[jj + 1] - mean) * rstd + be;
            nn[j] = h2pk(v0, v1);
        }
        cpk[h] = make_uint4(cc[0], cc[1], cc[2], cc[3]);
        npk[h] = make_uint4(nn[0], nn[1], nn[2], nn[3]);
    }
    *(uint4*)(convo + pr)     = cpk[0];
    *(uint4*)(convo + pr + 4) = cpk[1];
    *(uint4*)(n1o + pr)       = npk[0];
    *(uint4*)(n1o + pr + 4)   = npk[1];
}

// ---------------- FP16 GEMM-NT, k-tile 32, fragment-prefetch ILP -------------
// mode 0: C = acc + ts_emb[te[b],e]   -> packed C0
// mode 4: z=0: Q=acc*0.125 -> C0; z=1: K -> C1; z=2: V -> C2   (packed)
// mode 3: Cf = acc + bo[e] + conv_fp16[m,e]  (fp32 out)
#define SP2 20               // smem row stride in pairs (16 data + 4 pad)
#define GARR 2560            // words per array per stage (128*20)
#define GST  (2*GARR)        // 5120 words per stage (A, B)
__global__ __launch_bounds__(256, 2) void fp16_gemm(
    const unsigned* __restrict__ Ag,
    const unsigned* __restrict__ B0, const unsigned* __restrict__ B1,
    const unsigned* __restrict__ B2,
    unsigned* __restrict__ C0, unsigned* __restrict__ C1, unsigned* __restrict__ C2,
    float* __restrict__ Cf, int mode, const int* __restrict__ te,
    const float* __restrict__ aux1, const unsigned* __restrict__ convp)
{
    __shared__ unsigned gsm[2 * GST];            // 40960 B static

    const unsigned* Bg = B0;
    unsigned* C = C0;
    float scale = 1.0f;
    if (mode == 4) {
        if (blockIdx.z == 1)      { Bg = B1; C = C1; }
        else if (blockIdx.z == 2) { Bg = B2; C = C2; }
        else                      { scale = 0.125f; }
    }

    const int t = threadIdx.x;
    const int row0 = blockIdx.y << 7, col0 = blockIdx.x << 7;
    const int lrow = t >> 1, lh8 = (t & 1) << 3;
    const size_t aoff = ((size_t)(row0 + lrow) << 8) + lh8;
    const size_t boff = ((size_t)(col0 + lrow) << 8) + lh8;
    const unsigned cta = su32(gsm);
    const unsigned sbase = cta + (unsigned)((lrow * SP2 + lh8) << 2);

    const int warp = t >> 5, lane = t & 31;
    const int gid = lane >> 2, tig = lane & 3;
    const int wm = warp & 1, wn = warp >> 1;

    const int arowr = (wm << 6) + (lane & 15);
    const unsigned acolB = (unsigned)(lane & 16);
    const int browr = (wn << 5) + (lane & 7) + (((lane >> 4) & 1) << 3);
    const unsigned bcolB = (unsigned)(((lane >> 3) & 1) << 4);

    float acc[4][4][4];
#pragma unroll
    for (int mt = 0; mt < 4; mt++)
#pragma unroll
        for (int nt = 0; nt < 4; nt++)
#pragma unroll
            for (int r = 0; r < 4; r++) acc[mt][nt][r] = 0.f;

#define GLOAD(kt, st) do {                                   \
        const unsigned kc = (unsigned)(kt) << 4;             \
        const unsigned sd = sbase + (st) * (GST << 2);       \
        CP16(sd,                    Ag + aoff + kc);         \
        CP16(sd + 16,               Ag + aoff + kc + 4);     \
        CP16(sd + (GARR << 2),      Bg + boff + kc);         \
        CP16(sd + (GARR << 2) + 16, Bg + boff + kc + 4);     \
    } while (0)

    GLOAD(0, 0); CP_COMMIT();
    GLOAD(1, 1); CP_COMMIT();

    for (int kt = 0; kt < 16; kt++) {
        CP_WAIT1();
        __syncthreads();
        const unsigned stB = cta + (kt & 1) * (GST << 2);

#pragma unroll
        for (int ks2 = 0; ks2 < 2; ks2++) {
            const unsigned kw = (unsigned)(ks2 << 3);
            // prefetch ALL fragments for this half-step first (ILP)
            unsigned bh[4][2], a[4][4];
#pragma unroll
            for (int ntp = 0; ntp < 2; ntp++) {
                const unsigned ba = stB +
                    ((GARR + (browr + (ntp << 4)) * SP2 + kw) << 2) + bcolB;
                ldsm_x4(bh[2*ntp][0], bh[2*ntp][1], bh[2*ntp+1][0], bh[2*ntp+1][1], ba);
            }
#pragma unroll
            for (int mt = 0; mt < 4; mt++) {
                const unsigned aa = stB +
                    (((arowr + (mt << 4)) * SP2 + kw) << 2) + acolB;
                ldsm_x4(a[mt][0], a[mt][1], a[mt][2], a[mt][3], aa);
            }
            // 16 back-to-back MMAs, no interleaved loads
#pragma unroll
            for (int mt = 0; mt < 4; mt++)
#pragma unroll
                for (int nt = 0; nt < 4; nt++)
                    mma16(acc[mt][nt], a[mt], bh[nt]);
        }
        __syncthreads();
        if (kt + 2 < 16) GLOAD(kt + 2, kt & 1);
        CP_COMMIT();
    }

    // ---- epilogue ----
    if (mode == 3) {
#pragma unroll
        for (int mt = 0; mt < 4; mt++) {
            const int r1 = row0 + (wm << 6) + (mt << 4) + gid;
            const int r2 = r1 + 8;
#pragma unroll
            for (int nt = 0; nt < 4; nt++) {
                const int c = col0 + (wn << 5) + (nt << 3) + (tig << 1);
                const float a0 = aux1[c], a1 = aux1[c + 1];
                const float2 cv1 = h2up(convp[((size_t)r1 << 8) + (c >> 1)]);
                const float2 cv2 = h2up(convp[((size_t)r2 << 8) + (c >> 1)]);
                float v0 = acc[mt][nt][0] + a0 + cv1.x;
                float v1 = acc[mt][nt][1] + a1 + cv1.y;
                float v2 = acc[mt][nt][2] + a0 + cv2.x;
                float v3 = acc[mt][nt][3] + a1 + cv2.y;
                *(float2*)(Cf + ((size_t)r1 << 9) + c) = make_float2(v0, v1);
                *(float2*)(Cf + ((size_t)r2 << 9) + c) = make_float2(v2, v3);
            }
        }
    } else {
        int e = 0;
        if (mode == 0) e = te[row0 >> 10];
#pragma unroll
        for (int mt = 0; mt < 4; mt++) {
            const int r1 = row0 + (wm << 6) + (mt << 4) + gid;
            const int r2 = r1 + 8;
#pragma unroll
            for (int nt = 0; nt < 4; nt++) {
                const int c = col0 + (wn << 5) + (nt << 3) + (tig << 1);
                float a0 = 0.f, a1 = 0.f;
                if (mode == 0) {
                    a0 = aux1[((size_t)e << 9) + c];
                    a1 = aux1[((size_t)e << 9) + c + 1];
                }
                const float v0 = acc[mt][nt][0] * scale + a0;
                const float v1 = acc[mt][nt][1] * scale + a1;
                const float v2 = acc[mt][nt][2] * scale + a0;
                const float v3 = acc[mt][nt][3] * scale + a1;
                C[((size_t)r1 << 8) + (c >> 1)] = h2pk(v0, v1);
                C[((size_t)r2 << 8) + (c >> 1)] = h2pk(v2, v3);
            }
        }
    }
}

// ---------------- FA2-style fp16 attention, static 18KB smem -----------------
// (unchanged — proven)
#define RS 36
#define STW 2304
__global__ __launch_bounds__(128, 4) void k_attn6(
    const unsigned* __restrict__ q, const unsigned* __restrict__ k,
    const unsigned* __restrict__ v, unsigned* __restrict__ ao)
{
    __shared__ unsigned smw[2 * STW];

    const int jt = (gridDim.x - 1) - blockIdx.x;
    const int h = blockIdx.y, b = blockIdx.z;
    const int j0 = jt << 6;
    const int t = threadIdx.x, warp = t >> 5, lane = t & 31;
    const int gid = lane >> 2, tig = lane & 3;
    const size_t rowb = ((size_t)b << 10);
    const int coff2 = h << 5;
    const unsigned sbase = su32(smw);

    const int lrow = t >> 2;
    const int lsub = (t & 3) << 3;

#define LOADQV(i0_, st_) do {                                                   \
        const size_t g_ = ((rowb + (unsigned)(i0_) + lrow) << 8) + coff2 + lsub; \
        const unsigned s_ = sbase + (((st_) * STW + lrow * RS + lsub) << 2);     \
        CP16(s_,                   q + g_);                                     \
        CP16(s_ + 16,              q + g_ + 4);                                 \
        CP16(s_ + (1152 << 2),     v + g_);                                     \
        CP16(s_ + (1152 << 2) + 16, v + g_ + 4);                                \
    } while (0)

    const int ntiles = (jt << 1) + 2;

    LOADQV(0, 0); CP_COMMIT();
    if (ntiles > 1) LOADQV(32, 1);
    CP_COMMIT();

    const int krow = j0 + (warp << 4) + gid;
    const size_t kg0 = ((rowb + krow) << 8) + coff2;
    const size_t kg8 = ((rowb + krow + 8) << 8) + coff2;
    unsigned kf[4][4];
#pragma unroll
    for (int ks = 0; ks < 4; ks++) {
        const int p = (ks << 3) + tig;
        kf[ks][0] = k[kg0 + p];     kf[ks][1] = k[kg8 + p];
        kf[ks][2] = k[kg0 + p + 4]; kf[ks][3] = k[kg8 + p + 4];
    }

    const int qrowrel = (lane & 7) + ((lane & 16) >> 1);
    const unsigned qcol = (lane & 8) >> 1;
    const int vrowrel = (lane & 7) + (lane & 8);
    const unsigned vcol = (lane & 16) >> 2;

    float m0 = NEGF, m1 = NEGF, l0 = 0.f, l1 = 0.f;
    float acc[8][4];
#pragma unroll
    for (int nb = 0; nb < 8; nb++)
#pragma unroll
        for (int r = 0; r < 4; r++) acc[nb][r] = 0.f;

    const int jr0 = j0 + (warp << 4) + gid, jr1 = jr0 + 8;

    for (int it = 0; it < ntiles; ++it) {
        CP_WAIT1();
        __syncthreads();
        const unsigned stw = (it & 1) * STW;

        float s[4][4];
#pragma unroll
        for (int nb = 0; nb < 4; nb++)
#pragma unroll
            for (int r = 0; r < 4; r++) s[nb][r] = 0.f;
#pragma unroll
        for (int ks = 0; ks < 4; ks++) {
            unsigned qb[4][2];
#pragma unroll
            for (int nbp = 0; nbp < 2; nbp++) {
                const unsigned qa = sbase +
                    ((stw + ((nbp << 4) + qrowrel) * RS + (ks << 3) + qcol) << 2);
                unsigned q0, q1, q2, q3;
                ldsm_x4(q0, q1, q2, q3, qa);
                qb[2*nbp][0] = q0; qb[2*nbp][1] = q1;
                qb[2*nbp+1][0] = q2; qb[2*nbp+1][1] = q3;
            }
#pragma unroll
            for (int u = 0; u < 4; u++) mma16(s[u], kf[ks], qb[u]);
        }

        if (it >= ntiles - 2) {
            const int i0 = it << 5;
#pragma unroll
            for (int nb = 0; nb < 4; nb++) {
                const int c = i0 + (nb << 3) + (tig << 1);
                if (c     > jr0) s[nb][0] = NEGF;
                if (c + 1 > jr0) s[nb][1] = NEGF;
                if (c     > jr1) s[nb][2] = NEGF;
                if (c + 1 > jr1) s[nb][3] = NEGF;
            }
        }

        float mt0 = NEGF, mt1 = NEGF;
#pragma unroll
        for (int nb = 0; nb < 4; nb++) {
            mt0 = fmaxf(mt0, fmaxf(s[nb][0], s[nb][1]));
            mt1 = fmaxf(mt1, fmaxf(s[nb][2], s[nb][3]));
        }
        mt0 = fmaxf(mt0, __shfl_xor_sync(0xffffffffu, mt0, 1));
        mt0 = fmaxf(mt0, __shfl_xor_sync(0xffffffffu, mt0, 2));
        mt1 = fmaxf(mt1, __shfl_xor_sync(0xffffffffu, mt1, 1));
        mt1 = fmaxf(mt1, __shfl_xor_sync(0xffffffffu, mt1, 2));
        const float mn0 = fmaxf(m0, mt0), mn1 = fmaxf(m1, mt1);
        const float sc0 = __expf(m0 - mn0), sc1 = __expf(m1 - mn1);
        m0 = mn0; m1 = mn1;

        float rs0 = 0.f, rs1 = 0.f;
#pragma unroll
        for (int nb = 0; nb < 4; nb++) {
            s[nb][0] = __expf(s[nb][0] - mn0);
            s[nb][1] = __expf(s[nb][1] - mn0);
            s[nb][2] = __expf(s[nb][2] - mn1);
            s[nb][3] = __expf(s[nb][3] - mn1);
            rs0 += s[nb][0] + s[nb][1];
            rs1 += s[nb][2] + s[nb][3];
        }
        rs0 += __shfl_xor_sync(0xffffffffu, rs0, 1);
        rs0 += __shfl_xor_sync(0xffffffffu, rs0, 2);
        rs1 += __shfl_xor_sync(0xffffffffu, rs1, 1);
        rs1 += __shfl_xor_sync(0xffffffffu, rs1, 2);
        l0 = l0 * sc0 + rs0;
        l1 = l1 * sc1 + rs1;

#pragma unroll
        for (int nb = 0; nb < 8; nb++) {
            acc[nb][0] *= sc0; acc[nb][1] *= sc0;
            acc[nb][2] *= sc1; acc[nb][3] *= sc1;
        }

#pragma unroll
        for (int kk = 0; kk < 2; kk++) {
            unsigned pa[4];
            pa[0] = h2pk(s[2*kk][0],     s[2*kk][1]);
            pa[1] = h2pk(s[2*kk][2],     s[2*kk][3]);
            pa[2] = h2pk(s[2*kk + 1][0], s[2*kk + 1][1]);
            pa[3] = h2pk(s[2*kk + 1][2], s[2*kk + 1][3]);
#pragma unroll
            for (int nbp = 0; nbp < 4; nbp++) {
                const unsigned va = sbase +
                    ((stw + 1152 + ((kk << 4) + vrowrel) * RS + (nbp << 3) + vcol) << 2);
                unsigned v0, v1, v2, v3;
                ldsm_x4t(v0, v1, v2, v3, va);
                unsigned vb0[2] = {v0, v1}, vb1[2] = {v2, v3};
                mma16(acc[2*nbp],     pa, vb0);
                mma16(acc[2*nbp + 1], pa, vb1);
            }
        }

        __syncthreads();
        if (it + 2 < ntiles) LOADQV((it + 2) << 5, it & 1);
        CP_COMMIT();
    }

    const float rl0 = 1.0f / l0, rl1 = 1.0f / l1;
    const size_t o1 = ((rowb + jr0) << 8) + coff2;
    const size_t o2 = ((rowb + jr1) << 8) + coff2;
#pragma unroll
    for (int nb = 0; nb < 8; nb++) {
        const int pp = (nb << 2) + tig;
        ao[o1 + pp] = h2pk(acc[nb][0] * rl0, acc[nb][1] * rl0);
        ao[o2 + pp] = h2pk(acc[nb][2] * rl1, acc[nb][3] * rl1);
    }
#undef LOADQV
}

// ---------------- kernel 4: LN2 + coalesced transpose to (B,D,S) -------------
__global__ __launch_bounds__(256) void k_ln2t(
    const float* __restrict__ res, const float* __restrict__ g2,
    const float* __restrict__ b2, float* __restrict__ out)
{
    __shared__ float sm[16 * 513];
    __shared__ float smean[16], srstd[16];

    const int blk = blockIdx.x;
    const int b = blk >> 6, s0 = (blk & 63) << 4;
    const int t = threadIdx.x;

    for (int i = t; i < 2048; i += 256) {
        const int r = i >> 7, c4 = (i & 127) << 2;
        const float4 v = *(const float4*)(res + ((size_t)((b << 10) + s0 + r) << 9) + c4);
        float* d = sm + r * 513 + c4;
        d[0] = v.x; d[1] = v.y; d[2] = v.z; d[3] = v.w;
    }
    __syncthreads();

    {
        const int r = t >> 4, tr = t & 15;
        float s1 = 0.f, s2 = 0.f;
        for (int kx = tr; kx < 512; kx += 16) {
            const float x = sm[r * 513 + kx];
            s1 += x; s2 += x * x;
        }
#pragma unroll
        for (int o = 8; o; o >>= 1) {
            s1 += __shfl_down_sync(0xffffffffu, s1, o, 16);
            s2 += __shfl_down_sync(0xffffffffu, s2, o, 16);
        }
        if (tr == 0) {
            const float mean = s1 * (1.0f / 512.0f);
            const float var  = (s2 - 512.0f * mean * mean) * (1.0f / 511.0f);
            smean[r] = mean;
            srstd[r] = rsqrtf(var + 1e-5f);
        }
    }
    __syncthreads();

    const float gg = g2[s0 + (t & 15)], be = b2[s0 + (t & 15)];
    for (int i = t; i < 8192; i += 256) {
        const int d = i >> 4, si = i & 15;
        const float x = sm[si * 513 + d];
        out[((size_t)((b << 9) + d) << 10) + s0 + si] =
            gg * (x - smean[si]) * srstd[si] + be;
    }
}

// ---------------- launch -----------------------------------------------------
extern "C" void kernel_launch(void* const* d_in, const int* in_sizes, int n_in,
                              void* d_out, int out_size)
{
    const float* ts     = (const float*)d_in[0];
    const int*   te     = (const int*)  d_in[1];
    const float* conv_w = (const float*)d_in[2];
    const float* conv_b = (const float*)d_in[3];
    const float* pe     = (const float*)d_in[4];
    const float* ts_emb = (const float*)d_in[5];
    const float* g1     = (const float*)d_in[6];
    const float* b1     = (const float*)d_in[7];
    const float* Mw     = (const float*)d_in[8];
    const float* Wq     = (const float*)d_in[9];
    const float* Wk     = (const float*)d_in[10];
    const float* Wv     = (const float*)d_in[11];
    const float* Wo     = (const float*)d_in[12];
    const float* bo     = (const float*)d_in[13];
    const float* g2     = (const float*)d_in[14];
    const float* b2     = (const float*)d_in[15];
    float* out = (float*)d_out;

    float* pr;
    unsigned *pc, *pn1, *pd, *pq, *pk, *pv, *pa;
    unsigned *wm, *wq, *wk, *wv, *wo;
    cudaGetSymbolAddress((void**)&pc,  g_conv);
    cudaGetSymbolAddress((void**)&pr,  g_res);
    cudaGetSymbolAddress((void**)&pn1, g_n1);
    cudaGetSymbolAddress((void**)&pd,  g_d);
    cudaGetSymbolAddress((void**)&pq,  g_q);
    cudaGetSymbolAddress((void**)&pk,  g_k);
    cudaGetSymbolAddress((void**)&pv,  g_v);
    cudaGetSymbolAddress((void**)&pa,  g_a);
    cudaGetSymbolAddress((void**)&wm,  g_wm);
    cudaGetSymbolAddress((void**)&wq,  g_wq);
    cudaGetSymbolAddress((void**)&wk,  g_wk);
    cudaGetSymbolAddress((void**)&wv,  g_wv);
    cudaGetSymbolAddress((void**)&wo,  g_wo);

    // weight packing (once per launch)
    const int n4 = DDIM * DDIM / 4;
    CvtTab tab;
    tab.in[0] = (const float4*)Mw; tab.o[0] = (uint2*)wm;
    tab.in[1] = (const float4*)Wq; tab.o[1] = (uint2*)wq;
    tab.in[2] = (const float4*)Wk; tab.o[2] = (uint2*)wk;
    tab.in[3] = (const float4*)Wv; tab.o[3] = (uint2*)wv;
    tab.in[4] = (const float4*)Wo; tab.o[4] = (uint2*)wo;
    k_cvt5<<<dim3(n4 / 256, 5), 256>>>(tab, n4);

    k_embed2<<<BSN / 8, 256>>>(ts, conv_w, conv_b, pe, g1, b1, pc, pn1);

    dim3 gg(4, 128, 1);
    fp16_gemm<<<gg, 256>>>(pn1, wm, nullptr, nullptr,
                           pd, nullptr, nullptr,
                           nullptr, 0, te, ts_emb, nullptr);
    dim3 gq(4, 128, 3);
    fp16_gemm<<<gq, 256>>>(pd, wq, wk, wv,
                           pq, pk, pv,
                           nullptr, 4, nullptr, nullptr, nullptr);

    k_attn6<<<dim3(SSZ / 64, 8, BB), 128>>>(pq, pk, pv, pa);

    fp16_gemm<<<gg, 256>>>(pa, wo, nullptr, nullptr,
                           nullptr, nullptr, nullptr,
                           pr, 3, nullptr, bo, pc);

    k_ln2t<<<BB * 64, 256>>>(pr, g2, b2, out);
}

// round 17
// speedup vs baseline: 1.0746x; 1.0746x over previous
#include <cuda_runtime.h>
#include <cuda_fp16.h>
#include <math.h>

#define BB   16
#define SSZ  1024
#define DDIM 512
#define PDIM 256            // packed fp16 pairs per row
#define BSN  (BB*SSZ)       // 16384 rows
#define NEGF (-1e30f)

// ---------------- scratch (device globals: allocation-free) ----------------
__device__ float    g_conv[BSN*DDIM];
__device__ float    g_res [BSN*DDIM];
__device__ unsigned g_n1[BSN*PDIM];
__device__ unsigned g_d [BSN*PDIM];
__device__ unsigned g_q [BSN*PDIM];
__device__ unsigned g_k [BSN*PDIM];
__device__ unsigned g_v [BSN*PDIM];
__device__ unsigned g_a [BSN*PDIM];
__device__ unsigned g_wm[DDIM*PDIM];
__device__ unsigned g_wq[DDIM*PDIM];
__device__ unsigned g_wk[DDIM*PDIM];
__device__ unsigned g_wv[DDIM*PDIM];
__device__ unsigned g_wo[DDIM*PDIM];

// ---------------- helpers ----------------------------------------------------
__device__ __forceinline__ unsigned h2pk(float x0, float x1) {
    __half2 h = __floats2half2_rn(x0, x1);
    return *(unsigned*)&h;
}
__device__ __forceinline__ void mma16(float* c, const unsigned* a, const unsigned* b) {
    asm volatile(
        "mma.sync.aligned.m16n8k16.row.col.f32.f16.f16.f32 "
        "{%0,%1,%2,%3}, {%4,%5,%6,%7}, {%8,%9}, {%0,%1,%2,%3};\n"
        : "+f"(c[0]), "+f"(c[1]), "+f"(c[2]), "+f"(c[3])
        : "r"(a[0]), "r"(a[1]), "r"(a[2]), "r"(a[3]), "r"(b[0]), "r"(b[1]));
}
__device__ __forceinline__ void ldsm_x4(unsigned& r0, unsigned& r1, unsigned& r2,
                                        unsigned& r3, unsigned addr) {
    asm volatile("ldmatrix.sync.aligned.m8n8.x4.shared.b16 {%0,%1,%2,%3}, [%4];"
        : "=r"(r0), "=r"(r1), "=r"(r2), "=r"(r3) : "r"(addr));
}
__device__ __forceinline__ void ldsm_x4t(unsigned& r0, unsigned& r1, unsigned& r2,
                                         unsigned& r3, unsigned addr) {
    asm volatile("ldmatrix.sync.aligned.m8n8.x4.trans.shared.b16 {%0,%1,%2,%3}, [%4];"
        : "=r"(r0), "=r"(r1), "=r"(r2), "=r"(r3) : "r"(addr));
}
__device__ __forceinline__ unsigned su32(const void* p) {
    return (unsigned)__cvta_generic_to_shared(p);
}
#define CP16(d, s) asm volatile("cp.async.cg.shared.global [%0], [%1], 16;\n" :: "r"(d), "l"(s))
#define CP_COMMIT()  asm volatile("cp.async.commit_group;\n")
#define CP_WAIT1()   asm volatile("cp.async.wait_group 1;\n")

// ---------------- kernel: fp32 -> packed fp16 for 5 weights ------------------
struct CvtTab { const float4* in[5]; uint2* o[5]; };
__global__ __launch_bounds__(256) void k_cvt5(CvtTab tab, int n4)
{
    const int w = blockIdx.y;
    int i = blockIdx.x * 256 + threadIdx.x;
    if (i >= n4) return;
    float4 v = tab.in[w][i];
    tab.o[w][i] = make_uint2(h2pk(v.x, v.y), h2pk(v.z, v.w));
}

// ---------------- kernel 1: conv + pe + gelu + LN1 (packed fp16 out) ---------
__global__ __launch_bounds__(128) void k_embed(
    const float* __restrict__ ts, const float* __restrict__ cw,
    const float* __restrict__ cb, const float* __restrict__ pe,
    const float* __restrict__ g1, const float* __restrict__ b1,
    float* __restrict__ convo, unsigned* __restrict__ n1o)
{
    const int bs = blockIdx.x;
    const int b = bs >> 10, s = bs & 1023;
    const int t = threadIdx.x;
    const int d0 = t << 2;
    const float* tp = ts + ((size_t)b << 12) + (s << 2);
    const float t0 = tp[0], t1 = tp[1], t2 = tp[2], t3 = tp[3];

    const float4 cb4 = *(const float4*)(cb + d0);
    const float4 pe4 = *(const float4*)(pe + ((size_t)s << 9) + d0);

    float cvv[4], act[4];
    float ls1 = 0.f, ls2 = 0.f;
#pragma unroll
    for (int j = 0; j < 4; j++) {
        const float4 w = *(const float4*)(cw + ((d0 + j) << 2));
        float c = fmaf(t0, w.x, fmaf(t1, w.y, fmaf(t2, w.z, t3 * w.w)));
        c += ((const float*)&cb4)[j] + ((const float*)&pe4)[j];
        cvv[j] = c;
        const float a = 0.5f * c * (1.0f + erff(c * 0.70710678118654752f));
        act[j] = a; ls1 += a; ls2 += a * a;
    }
    *(float4*)(convo + ((size_t)bs << 9) + d0) = make_float4(cvv[0], cvv[1], cvv[2], cvv[3]);

    __shared__ float sa[4], sb[4];
#pragma unroll
    for (int o = 16; o; o >>= 1) {
        ls1 += __shfl_down_sync(0xffffffffu, ls1, o);
        ls2 += __shfl_down_sync(0xffffffffu, ls2, o);
    }
    if ((t & 31) == 0) { sa[t >> 5] = ls1; sb[t >> 5] = ls2; }
    __syncthreads();
    const float S1 = sa[0] + sa[1] + sa[2] + sa[3];
    const float S2 = sb[0] + sb[1] + sb[2] + sb[3];
    const float mean = S1 * (1.0f / 512.0f);
    const float var  = (S2 - 512.0f * mean * mean) * (1.0f / 511.0f);  // ddof=1
    const float rstd = rsqrtf(var + 1e-5f);
    const float gg = g1[s], be = b1[s];

    float v[4];
#pragma unroll
    for (int j = 0; j < 4; j++) v[j] = gg * (act[j] - mean) * rstd + be;
    const size_t pr = ((size_t)bs << 8) + (t << 1);
    *(uint2*)(n1o + pr) = make_uint2(h2pk(v[0], v[1]), h2pk(v[2], v[3]));
}

// ---------------- FP16 GEMM-NT, 512 threads / 16 warps (occupancy) -----------
// 128x128 tile, warp grid 4(m) x 4(n), warp tile 32x32, k-tile 32.
// mode 0: C = acc + ts_emb[te[b],e]   -> packed C0
// mode 4: z=0: Q=acc*0.125 -> C0; z=1: K -> C1; z=2: V -> C2   (packed)
// mode 3: Cf = acc + bo[e] + conv[m,e]  (fp32 out)
#define SP2 20               // smem row stride in pairs (16 data + 4 pad)
#define GARR 2560            // words per array per stage (128*20)
#define GST  (2*GARR)        // 5120 words per stage (A, B)
__global__ __launch_bounds__(512, 2) void fp16_gemm(
    const unsigned* __restrict__ Ag,
    const unsigned* __restrict__ B0, const unsigned* __restrict__ B1,
    const unsigned* __restrict__ B2,
    unsigned* __restrict__ C0, unsigned* __restrict__ C1, unsigned* __restrict__ C2,
    float* __restrict__ Cf, int mode, const int* __restrict__ te,
    const float* __restrict__ aux1, const float* __restrict__ aux2)
{
    __shared__ unsigned gsm[2 * GST];            // 40960 B static

    const unsigned* Bg = B0;
    unsigned* C = C0;
    float scale = 1.0f;
    if (mode == 4) {
        if (blockIdx.z == 1)      { Bg = B1; C = C1; }
        else if (blockIdx.z == 2) { Bg = B2; C = C2; }
        else                      { scale = 0.125f; }
    }

    const int t = threadIdx.x;
    const int row0 = blockIdx.y << 7, col0 = blockIdx.x << 7;
    const int lrow = t >> 2, lsub = (t & 3) << 2;      // 4 pairs per thread
    const size_t aoff = ((size_t)(row0 + lrow) << 8) + lsub;
    const size_t boff = ((size_t)(col0 + lrow) << 8) + lsub;
    const unsigned cta = su32(gsm);
    const unsigned sbase = cta + (unsigned)((lrow * SP2 + lsub) << 2);

    const int warp = t >> 5, lane = t & 31;
    const int gid = lane >> 2, tig = lane & 3;
    const int wm = warp & 3, wn = warp >> 2;           // 4 x 4 warp grid

    const int arowr = (wm << 5) + (lane & 15);
    const unsigned acolB = (unsigned)(lane & 16);
    const int browr = (wn << 5) + (lane & 7) + (((lane >> 4) & 1) << 3);
    const unsigned bcolB = (unsigned)(((lane >> 3) & 1) << 4);

    float acc[2][4][4];
#pragma unroll
    for (int mt = 0; mt < 2; mt++)
#pragma unroll
        for (int nt = 0; nt < 4; nt++)
#pragma unroll
            for (int r = 0; r < 4; r++) acc[mt][nt][r] = 0.f;

#define GLOAD(kt, st) do {                                   \
        const unsigned kc = (unsigned)(kt) << 4;             \
        const unsigned sd = sbase + (st) * (GST << 2);       \
        CP16(sd,               Ag + aoff + kc);              \
        CP16(sd + (GARR << 2), Bg + boff + kc);              \
    } while (0)

    GLOAD(0, 0); CP_COMMIT();
    GLOAD(1, 1); CP_COMMIT();

    for (int kt = 0; kt < 16; kt++) {
        CP_WAIT1();
        __syncthreads();
        const unsigned stB = cta + (kt & 1) * (GST << 2);

#pragma unroll
        for (int ks2 = 0; ks2 < 2; ks2++) {
            const unsigned kw = (unsigned)(ks2 << 3);
            unsigned bh[4][2], a[2][4];
#pragma unroll
            for (int ntp = 0; ntp < 2; ntp++) {
                const unsigned ba = stB +
                    ((GARR + (browr + (ntp << 4)) * SP2 + kw) << 2) + bcolB;
                ldsm_x4(bh[2*ntp][0], bh[2*ntp][1], bh[2*ntp+1][0], bh[2*ntp+1][1], ba);
            }
#pragma unroll
            for (int mt = 0; mt < 2; mt++) {
                const unsigned aa = stB +
                    (((arowr + (mt << 4)) * SP2 + kw) << 2) + acolB;
                ldsm_x4(a[mt][0], a[mt][1], a[mt][2], a[mt][3], aa);
            }
#pragma unroll
            for (int mt = 0; mt < 2; mt++)
#pragma unroll
                for (int nt = 0; nt < 4; nt++)
                    mma16(acc[mt][nt], a[mt], bh[nt]);
        }
        __syncthreads();
        if (kt + 2 < 16) GLOAD(kt + 2, kt & 1);
        CP_COMMIT();
    }

    // ---- epilogue ----
    if (mode == 3) {
#pragma unroll
        for (int mt = 0; mt < 2; mt++) {
            const int r1 = row0 + (wm << 5) + (mt << 4) + gid;
            const int r2 = r1 + 8;
#pragma unroll
            for (int nt = 0; nt < 4; nt++) {
                const int c = col0 + (wn << 5) + (nt << 3) + (tig << 1);
                const float a0 = aux1[c], a1 = aux1[c + 1];
                float v0 = acc[mt][nt][0] + a0 + aux2[((size_t)r1 << 9) + c];
                float v1 = acc[mt][nt][1] + a1 + aux2[((size_t)r1 << 9) + c + 1];
                float v2 = acc[mt][nt][2] + a0 + aux2[((size_t)r2 << 9) + c];
                float v3 = acc[mt][nt][3] + a1 + aux2[((size_t)r2 << 9) + c + 1];
                *(float2*)(Cf + ((size_t)r1 << 9) + c) = make_float2(v0, v1);
                *(float2*)(Cf + ((size_t)r2 << 9) + c) = make_float2(v2, v3);
            }
        }
    } else {
        int e = 0;
        if (mode == 0) e = te[row0 >> 10];
#pragma unroll
        for (int mt = 0; mt < 2; mt++) {
            const int r1 = row0 + (wm << 5) + (mt << 4) + gid;
            const int r2 = r1 + 8;
#pragma unroll
            for (int nt = 0; nt < 4; nt++) {
                const int c = col0 + (wn << 5) + (nt << 3) + (tig << 1);
                float a0 = 0.f, a1 = 0.f;
                if (mode == 0) {
                    a0 = aux1[((size_t)e << 9) + c];
                    a1 = aux1[((size_t)e << 9) + c + 1];
                }
                const float v0 = acc[mt][nt][0] * scale + a0;
                const float v1 = acc[mt][nt][1] * scale + a1;
                const float v2 = acc[mt][nt][2] * scale + a0;
                const float v3 = acc[mt][nt][3] * scale + a1;
                C[((size_t)r1 << 8) + (c >> 1)] = h2pk(v0, v1);
                C[((size_t)r2 << 8) + (c >> 1)] = h2pk(v2, v3);
            }
        }
    }
}

// ---------------- FA2-style fp16 attention, static 18KB smem -----------------
// (unchanged — proven at ~55us)
#define RS 36
#define STW 2304
__global__ __launch_bounds__(128, 4) void k_attn6(
    const unsigned* __restrict__ q, const unsigned* __restrict__ k,
    const unsigned* __restrict__ v, unsigned* __restrict__ ao)
{
    __shared__ unsigned smw[2 * STW];

    const int jt = (gridDim.x - 1) - blockIdx.x;
    const int h = blockIdx.y, b = blockIdx.z;
    const int j0 = jt << 6;
    const int t = threadIdx.x, warp = t >> 5, lane = t & 31;
    const int gid = lane >> 2, tig = lane & 3;
    const size_t rowb = ((size_t)b << 10);
    const int coff2 = h << 5;
    const unsigned sbase = su32(smw);

    const int lrow = t >> 2;
    const int lsub = (t & 3) << 3;

#define LOADQV(i0_, st_) do {                                                   \
        const size_t g_ = ((rowb + (unsigned)(i0_) + lrow) << 8) + coff2 + lsub; \
        const unsigned s_ = sbase + (((st_) * STW + lrow * RS + lsub) << 2);     \
        CP16(s_,                   q + g_);                                     \
        CP16(s_ + 16,              q + g_ + 4);                                 \
        CP16(s_ + (1152 << 2),     v + g_);                                     \
        CP16(s_ + (1152 << 2) + 16, v + g_ + 4);                                \
    } while (0)

    const int ntiles = (jt << 1) + 2;

    LOADQV(0, 0); CP_COMMIT();
    if (ntiles > 1) LOADQV(32, 1);
    CP_COMMIT();

    const int krow = j0 + (warp << 4) + gid;
    const size_t kg0 = ((rowb + krow) << 8) + coff2;
    const size_t kg8 = ((rowb + krow + 8) << 8) + coff2;
    unsigned kf[4][4];
#pragma unroll
    for (int ks = 0; ks < 4; ks++) {
        const int p = (ks << 3) + tig;
        kf[ks][0] = k[kg0 + p];     kf[ks][1] = k[kg8 + p];
        kf[ks][2] = k[kg0 + p + 4]; kf[ks][3] = k[kg8 + p + 4];
    }

    const int qrowrel = (lane & 7) + ((lane & 16) >> 1);
    const unsigned qcol = (lane & 8) >> 1;
    const int vrowrel = (lane & 7) + (lane & 8);
    const unsigned vcol = (lane & 16) >> 2;

    float m0 = NEGF, m1 = NEGF, l0 = 0.f, l1 = 0.f;
    float acc[8][4];
#pragma unroll
    for (int nb = 0; nb < 8; nb++)
#pragma unroll
        for (int r = 0; r < 4; r++) acc[nb][r] = 0.f;

    const int jr0 = j0 + (warp << 4) + gid, jr1 = jr0 + 8;

    for (int it = 0; it < ntiles; ++it) {
        CP_WAIT1();
        __syncthreads();
        const unsigned stw = (it & 1) * STW;

        float s[4][4];
#pragma unroll
        for (int nb = 0; nb < 4; nb++)
#pragma unroll
            for (int r = 0; r < 4; r++) s[nb][r] = 0.f;
#pragma unroll
        for (int ks = 0; ks < 4; ks++) {
            unsigned qb[4][2];
#pragma unroll
            for (int nbp = 0; nbp < 2; nbp++) {
                const unsigned qa = sbase +
                    ((stw + ((nbp << 4) + qrowrel) * RS + (ks << 3) + qcol) << 2);
                unsigned q0, q1, q2, q3;
                ldsm_x4(q0, q1, q2, q3, qa);
                qb[2*nbp][0] = q0; qb[2*nbp][1] = q1;
                qb[2*nbp+1][0] = q2; qb[2*nbp+1][1] = q3;
            }
#pragma unroll
            for (int u = 0; u < 4; u++) mma16(s[u], kf[ks], qb[u]);
        }

        if (it >= ntiles - 2) {
            const int i0 = it << 5;
#pragma unroll
            for (int nb = 0; nb < 4; nb++) {
                const int c = i0 + (nb << 3) + (tig << 1);
                if (c     > jr0) s[nb][0] = NEGF;
                if (c + 1 > jr0) s[nb][1] = NEGF;
                if (c     > jr1) s[nb][2] = NEGF;
                if (c + 1 > jr1) s[nb][3] = NEGF;
            }
        }

        float mt0 = NEGF, mt1 = NEGF;
#pragma unroll
        for (int nb = 0; nb < 4; nb++) {
            mt0 = fmaxf(mt0, fmaxf(s[nb][0], s[nb][1]));
            mt1 = fmaxf(mt1, fmaxf(s[nb][2], s[nb][3]));
        }
        mt0 = fmaxf(mt0, __shfl_xor_sync(0xffffffffu, mt0, 1));
        mt0 = fmaxf(mt0, __shfl_xor_sync(0xffffffffu, mt0, 2));
        mt1 = fmaxf(mt1, __shfl_xor_sync(0xffffffffu, mt1, 1));
        mt1 = fmaxf(mt1, __shfl_xor_sync(0xffffffffu, mt1, 2));
        const float mn0 = fmaxf(m0, mt0), mn1 = fmaxf(m1, mt1);
        const float sc0 = __expf(m0 - mn0), sc1 = __expf(m1 - mn1);
        m0 = mn0; m1 = mn1;

        float rs0 = 0.f, rs1 = 0.f;
#pragma unroll
        for (int nb = 0; nb < 4; nb++) {
            s[nb][0] = __expf(s[nb][0] - mn0);
            s[nb][1] = __expf(s[nb][1] - mn0);
            s[nb][2] = __expf(s[nb][2] - mn1);
            s[nb][3] = __expf(s[nb][3] - mn1);
            rs0 += s[nb][0] + s[nb][1];
            rs1 += s[nb][2] + s[nb][3];
        }
        rs0 += __shfl_xor_sync(0xffffffffu, rs0, 1);
        rs0 += __shfl_xor_sync(0xffffffffu, rs0, 2);
        rs1 += __shfl_xor_sync(0xffffffffu, rs1, 1);
        rs1 += __shfl_xor_sync(0xffffffffu, rs1, 2);
        l0 = l0 * sc0 + rs0;
        l1 = l1 * sc1 + rs1;

#pragma unroll
        for (int nb = 0; nb < 8; nb++) {
            acc[nb][0] *= sc0; acc[nb][1] *= sc0;
            acc[nb][2] *= sc1; acc[nb][3] *= sc1;
        }

#pragma unroll
        for (int kk = 0; kk < 2; kk++) {
            unsigned pa[4];
            pa[0] = h2pk(s[2*kk][0],     s[2*kk][1]);
            pa[1] = h2pk(s[2*kk][2],     s[2*kk][3]);
            pa[2] = h2pk(s[2*kk + 1][0], s[2*kk + 1][1]);
            pa[3] = h2pk(s[2*kk + 1][2], s[2*kk + 1][3]);
#pragma unroll
            for (int nbp = 0; nbp < 4; nbp++) {
                const unsigned va = sbase +
                    ((stw + 1152 + ((kk << 4) + vrowrel) * RS + (nbp << 3) + vcol) << 2);
                unsigned v0, v1, v2, v3;
                ldsm_x4t(v0, v1, v2, v3, va);
                unsigned vb0[2] = {v0, v1}, vb1[2] = {v2, v3};
                mma16(acc[2*nbp],     pa, vb0);
                mma16(acc[2*nbp + 1], pa, vb1);
            }
        }

        __syncthreads();
        if (it + 2 < ntiles) LOADQV((it + 2) << 5, it & 1);
        CP_COMMIT();
    }

    const float rl0 = 1.0f / l0, rl1 = 1.0f / l1;
    const size_t o1 = ((rowb + jr0) << 8) + coff2;
    const size_t o2 = ((rowb + jr1) << 8) + coff2;
#pragma unroll
    for (int nb = 0; nb < 8; nb++) {
        const int pp = (nb << 2) + tig;
        ao[o1 + pp] = h2pk(acc[nb][0] * rl0, acc[nb][1] * rl0);
        ao[o2 + pp] = h2pk(acc[nb][2] * rl1, acc[nb][3] * rl1);
    }
#undef LOADQV
}

// ---------------- kernel 4: LN2 + coalesced transpose to (B,D,S) -------------
__global__ __launch_bounds__(256) void k_ln2t(
    const float* __restrict__ res, const float* __restrict__ g2,
    const float* __restrict__ b2, float* __restrict__ out)
{
    __shared__ float sm[16 * 513];
    __shared__ float smean[16], srstd[16];

    const int blk = blockIdx.x;
    const int b = blk >> 6, s0 = (blk & 63) << 4;
    const int t = threadIdx.x;

    for (int i = t; i < 2048; i += 256) {
        const int r = i >> 7, c4 = (i & 127) << 2;
        const float4 v = *(const float4*)(res + ((size_t)((b << 10) + s0 + r) << 9) + c4);
        float* d = sm + r * 513 + c4;
        d[0] = v.x; d[1] = v.y; d[2] = v.z; d[3] = v.w;
    }
    __syncthreads();

    {
        const int r = t >> 4, tr = t & 15;
        float s1 = 0.f, s2 = 0.f;
        for (int kx = tr; kx < 512; kx += 16) {
            const float x = sm[r * 513 + kx];
            s1 += x; s2 += x * x;
        }
#pragma unroll
        for (int o = 8; o; o >>= 1) {
            s1 += __shfl_down_sync(0xffffffffu, s1, o, 16);
            s2 += __shfl_down_sync(0xffffffffu, s2, o, 16);
        }
        if (tr == 0) {
            const float mean = s1 * (1.0f / 512.0f);
            const float var  = (s2 - 512.0f * mean * mean) * (1.0f / 511.0f);
            smean[r] = mean;
            srstd[r] = rsqrtf(var + 1e-5f);
        }
    }
    __syncthreads();

    const float gg = g2[s0 + (t & 15)], be = b2[s0 + (t & 15)];
    for (int i = t; i < 8192; i += 256) {
        const int d = i >> 4, si = i & 15;
        const float x = sm[si * 513 + d];
        out[((size_t)((b << 9) + d) << 10) + s0 + si] =
            gg * (x - smean[si]) * srstd[si] + be;
    }
}

// ---------------- launch -----------------------------------------------------
extern "C" void kernel_launch(void* const* d_in, const int* in_sizes, int n_in,
                              void* d_out, int out_size)
{
    const float* ts     = (const float*)d_in[0];
    const int*   te     = (const int*)  d_in[1];
    const float* conv_w = (const float*)d_in[2];
    const float* conv_b = (const float*)d_in[3];
    const float* pe     = (const float*)d_in[4];
    const float* ts_emb = (const float*)d_in[5];
    const float* g1     = (const float*)d_in[6];
    const float* b1     = (const float*)d_in[7];
    const float* Mw     = (const float*)d_in[8];
    const float* Wq     = (const float*)d_in[9];
    const float* Wk     = (const float*)d_in[10];
    const float* Wv     = (const float*)d_in[11];
    const float* Wo     = (const float*)d_in[12];
    const float* bo     = (const float*)d_in[13];
    const float* g2     = (const float*)d_in[14];
    const float* b2     = (const float*)d_in[15];
    float* out = (float*)d_out;

    float *pc, *pr;
    unsigned *pn1, *pd, *pq, *pk, *pv, *pa;
    unsigned *wm, *wq, *wk, *wv, *wo;
    cudaGetSymbolAddress((void**)&pc,  g_conv);
    cudaGetSymbolAddress((void**)&pr,  g_res);
    cudaGetSymbolAddress((void**)&pn1, g_n1);
    cudaGetSymbolAddress((void**)&pd,  g_d);
    cudaGetSymbolAddress((void**)&pq,  g_q);
    cudaGetSymbolAddress((void**)&pk,  g_k);
    cudaGetSymbolAddress((void**)&pv,  g_v);
    cudaGetSymbolAddress((void**)&pa,  g_a);
    cudaGetSymbolAddress((void**)&wm,  g_wm);
    cudaGetSymbolAddress((void**)&wq,  g_wq);
    cudaGetSymbolAddress((void**)&wk,  g_wk);
    cudaGetSymbolAddress((void**)&wv,  g_wv);
    cudaGetSymbolAddress((void**)&wo,  g_wo);

    // weight packing (once per launch)
    const int n4 = DDIM * DDIM / 4;
    CvtTab tab;
    tab.in[0] = (const float4*)Mw; tab.o[0] = (uint2*)wm;
    tab.in[1] = (const float4*)Wq; tab.o[1] = (uint2*)wq;
    tab.in[2] = (const float4*)Wk; tab.o[2] = (uint2*)wk;
    tab.in[3] = (const float4*)Wv; tab.o[3] = (uint2*)wv;
    tab.in[4] = (const float4*)Wo; tab.o[4] = (uint2*)wo;
    k_cvt5<<<dim3(n4 / 256, 5), 256>>>(tab, n4);

    k_embed<<<BSN, 128>>>(ts, conv_w, conv_b, pe, g1, b1, pc, pn1);

    dim3 gg(4, 128, 1);
    fp16_gemm<<<gg, 512>>>(pn1, wm, nullptr, nullptr,
                           pd, nullptr, nullptr,
                           nullptr, 0, te, ts_emb, nullptr);
    dim3 gq(4, 128, 3);
    fp16_gemm<<<gq, 512>>>(pd, wq, wk, wv,
                           pq, pk, pv,
                           nullptr, 4, nullptr, nullptr, nullptr);

    k_attn6<<<dim3(SSZ / 64, 8, BB), 128>>>(pq, pk, pv, pa);

    fp16_gemm<<<gg, 512>>>(pa, wo, nullptr, nullptr,
                           nullptr, nullptr, nullptr,
                           pr, 3, nullptr, bo, pc);

    k_ln2t<<<BB * 64, 256>>>(pr, g2, b2, out);
}